// round 2
// baseline (speedup 1.0000x reference)
#include <cuda_runtime.h>
#include <cstdint>
#include <cstddef>

// ====================== problem constants ======================
#define HW     1024
#define NCONV  2048          // 512 active blocks * 4 tiles (16x16 px)
#define NTOT   3072          // + 1024 zero-fill block items

// ====================== smem layout (float words) ==============
// [0:64)     scale[64]
// [64:128)   bias[64]
// [128:20864)       patch 18*18*64 f32 (swizzled channels)
// [20864:57728)     Bp: weights fragment-packed, 36864 floats (147456B)
#define S_SCALE_W 0
#define S_BIAS_W  64
#define S_PATCH_W 128
#define S_BP_W    20864
#define S_TOTAL_B 230912     // 57728 * 4 bytes  (<= 232448 opt-in)

// ====================== device globals =========================
__device__ __align__(16) float4 g_wB[9216];   // [tp=36][co=64][q=4] float4
__device__ int   g_flag[1024];
__device__ float g_sc[64];
__device__ float g_bi[64];

// ====================== helpers ================================
__device__ __forceinline__ float to_tf32(float x) {
    uint32_t u;
    asm("cvt.rna.tf32.f32 %0, %1;" : "=r"(u) : "f"(x));
    return __uint_as_float(u);
}

__device__ __forceinline__ void mma8(float* c,
                                     uint32_t a0, uint32_t a1, uint32_t a2, uint32_t a3,
                                     uint32_t b0, uint32_t b1) {
    asm volatile(
        "mma.sync.aligned.m16n8k8.row.col.f32.tf32.tf32.f32 "
        "{%0,%1,%2,%3}, {%4,%5,%6,%7}, {%8,%9}, {%0,%1,%2,%3};"
        : "+f"(c[0]), "+f"(c[1]), "+f"(c[2]), "+f"(c[3])
        : "r"(a0), "r"(a1), "r"(a2), "r"(a3), "r"(b0), "r"(b1));
}

// ====================== prep kernels ===========================
// Pack weights into fragment order: for k-step pair tp, co n, lane-quad q:
//   float4 = { W[16tp+q], W[16tp+q+4], W[16tp+q+8], W[16tp+q+12] }  (tf32-rounded)
// where W[k] = conv_w[tap(k)][ci(k)][n], k = tap*64 + ci.
// Also: clear flags, fold conv bias + BN into per-co scale/bias.
__global__ void prep1(const float* __restrict__ w,  const float* __restrict__ cb,
                      const float* __restrict__ gm, const float* __restrict__ bt,
                      const float* __restrict__ mn, const float* __restrict__ vr) {
    int idx = blockIdx.x * blockDim.x + threadIdx.x;
    if (idx < 9216) {
        int q  = idx & 3;
        int n  = (idx >> 2) & 63;
        int tp = idx >> 8;
        float v[4];
        #pragma unroll
        for (int j = 0; j < 4; j++) {
            int k   = 16 * tp + q + 4 * j;
            int tap = k >> 6, ci = k & 63;
            v[j] = to_tf32(w[(tap * 64 + ci) * 64 + n]);
        }
        g_wB[idx] = make_float4(v[0], v[1], v[2], v[3]);
    }
    if (idx < 1024) g_flag[idx] = 0;
    if (idx < 64) {
        float s = gm[idx] * rsqrtf(vr[idx] + 1e-3f);
        g_sc[idx] = s;
        g_bi[idx] = cb[idx] * s + bt[idx] - mn[idx] * s;
    }
}

__global__ void prep2(const int* __restrict__ abi) {
    int m = blockIdx.x * blockDim.x + threadIdx.x;
    if (m < 512) g_flag[abi[3 * m + 1] * 32 + abi[3 * m + 2]] = 1;
}

// ====================== main persistent kernel =================
// 148 CTAs x 256 threads, 1 CTA/SM. Items 0..2047: conv tiles (16x16 px,
// M=256,N=64,K=576 implicit GEMM via mma.sync tf32). Items 2048..3071:
// zero-fill for inactive 32x32 blocks.
__global__ void __launch_bounds__(256, 1)
convk(const float* __restrict__ inp, const int* __restrict__ abi,
      float* __restrict__ out) {
    extern __shared__ float sm[];
    const int tid  = threadIdx.x;
    const int wid  = tid >> 5;
    const int lane = tid & 31;
    const int grp  = lane >> 2;      // 0..7
    const int q    = lane & 3;       // 0..3

    // ---- stage weights (once) + scale/bias ----
    {
        float4* bp = (float4*)(sm + S_BP_W);
        #pragma unroll 4
        for (int f = tid; f < 9216; f += 256) bp[f] = g_wB[f];
        if (tid < 64) { sm[S_SCALE_W + tid] = g_sc[tid]; sm[S_BIAS_W + tid] = g_bi[tid]; }
    }

    const int rb    = (wid >> 1) * 4;    // warp's pixel-row base within tile
    const int nbase = (wid & 1) * 32;    // warp's output-channel base

    for (int it = blockIdx.x; it < NTOT; it += gridDim.x) {
        if (it < NCONV) {
            // ================= conv tile =================
            const int b   = it >> 2;
            const int sub = it & 3;
            const int bi  = abi[3 * b + 1];
            const int bj  = abi[3 * b + 2];
            const int gr0 = bi * 32 + (sub >> 1) * 16;
            const int gc0 = bj * 32 + (sub & 1) * 16;

            __syncthreads();   // protect patch smem from previous tile's readers

            // ---- load 18x18x64 patch (tf32-rounded, channel-swizzled) ----
            // swizzle: ci' = ci ^ (((pcol&3)<<3) | (pcol&4))  -> conflict-free frags
            {
                float4 tv[7];
                #pragma unroll 1
                for (int bb = 0; bb < 3; bb++) {
                    #pragma unroll
                    for (int u = 0; u < 7; u++) {
                        int f = tid + (bb * 7 + u) * 256;
                        float4 v = make_float4(0.f, 0.f, 0.f, 0.f);
                        if (f < 5184) {
                            int prow = f / 288;
                            int rem  = f - prow * 288;
                            int pcol = rem >> 4, c4 = rem & 15;
                            int ir = gr0 - 1 + prow, ic = gc0 - 1 + pcol;
                            if ((unsigned)ir < (unsigned)HW && (unsigned)ic < (unsigned)HW)
                                v = *(const float4*)(inp + ((size_t)ir * HW + ic) * 64 + c4 * 4);
                        }
                        tv[u] = v;
                    }
                    #pragma unroll
                    for (int u = 0; u < 7; u++) {
                        int f = tid + (bb * 7 + u) * 256;
                        if (f < 5184) {
                            int prow = f / 288;
                            int rem  = f - prow * 288;
                            int pcol = rem >> 4, c4 = rem & 15;
                            int sw   = ((pcol & 3) << 3) | (pcol & 4);
                            float4 v = tv[u];
                            v.x = to_tf32(v.x); v.y = to_tf32(v.y);
                            v.z = to_tf32(v.z); v.w = to_tf32(v.w);
                            *(float4*)(sm + S_PATCH_W + (prow * 18 + pcol) * 64
                                       + ((c4 * 4) ^ sw)) = v;
                        }
                    }
                }
            }
            __syncthreads();

            // ---- K loop: 36 pairs of k-steps (K=576, 8 per mma) ----
            float acc[4][4][4];
            #pragma unroll
            for (int a = 0; a < 4; a++)
                #pragma unroll
                for (int c = 0; c < 4; c++)
                    #pragma unroll
                    for (int d = 0; d < 4; d++) acc[a][c][d] = 0.f;

            const float*  patch = sm + S_PATCH_W;
            const float4* bp    = (const float4*)(sm + S_BP_W);

            #pragma unroll 1
            for (int t2 = 0; t2 < 36; t2++) {
                const int tap = t2 >> 2;                       // 0..8
                const int kh  = (tap >= 6) ? 2 : (tap >= 3 ? 1 : 0);
                const int kw  = tap - kh * 3;

                float4 bf[4];
                #pragma unroll
                for (int nf = 0; nf < 4; nf++)
                    bf[nf] = bp[(t2 * 64 + nbase + nf * 8 + grp) * 4 + q];

                const int pc    = grp + kw;                    // 0..9
                const int sw    = ((pc & 3) << 3) | (pc & 4);
                const int cib0  = ((2 * t2) & 7) << 3;
                const int base0 = ((rb + kh) * 18 + pc) * 64;

                #pragma unroll
                for (int hv = 0; hv < 2; hv++) {
                    const int cib = cib0 + hv * 8;
                    const int e0  = (cib + q) ^ sw;
                    const int e1  = e0 ^ 4;
                    #pragma unroll
                    for (int mf = 0; mf < 4; mf++) {
                        const int ba = base0 + mf * 1152;      // next pixel row
                        uint32_t a0 = __float_as_uint(patch[ba + e0]);
                        uint32_t a1 = __float_as_uint(patch[ba + 512 + e0]);
                        uint32_t a2 = __float_as_uint(patch[ba + e1]);
                        uint32_t a3 = __float_as_uint(patch[ba + 512 + e1]);
                        #pragma unroll
                        for (int nf = 0; nf < 4; nf++) {
                            uint32_t b0 = __float_as_uint(hv ? bf[nf].z : bf[nf].x);
                            uint32_t b1 = __float_as_uint(hv ? bf[nf].w : bf[nf].y);
                            mma8(acc[mf][nf], a0, a1, a2, a3, b0, b1);
                        }
                    }
                }
            }

            // ---- epilogue: BN-fused scale/bias + ReLU, float2 stores ----
            #pragma unroll
            for (int mf = 0; mf < 4; mf++) {
                const int gpr = gr0 + rb + mf;
                #pragma unroll
                for (int nf = 0; nf < 4; nf++) {
                    const int n0 = nbase + nf * 8 + 2 * q;
                    const float s0 = sm[S_SCALE_W + n0], s1 = sm[S_SCALE_W + n0 + 1];
                    const float d0 = sm[S_BIAS_W + n0],  d1 = sm[S_BIAS_W + n0 + 1];
                    float* p0 = out + ((size_t)gpr * HW + gc0 + grp) * 64 + n0;
                    float2 v0, v1;
                    v0.x = fmaxf(fmaf(acc[mf][nf][0], s0, d0), 0.f);
                    v0.y = fmaxf(fmaf(acc[mf][nf][1], s1, d1), 0.f);
                    v1.x = fmaxf(fmaf(acc[mf][nf][2], s0, d0), 0.f);
                    v1.y = fmaxf(fmaf(acc[mf][nf][3], s1, d1), 0.f);
                    __stcs((float2*)p0, v0);
                    __stcs((float2*)(p0 + 8 * 64), v1);        // pixel col grp+8
                }
            }
        } else {
            // ================= zero-fill item =================
            const int blk = it - NCONV;
            if (!g_flag[blk]) {
                const int bi = blk >> 5, bj = blk & 31;
                const float4 z = make_float4(0.f, 0.f, 0.f, 0.f);
                #pragma unroll 8
                for (int j = 0; j < 64; j++) {
                    int idx = tid + j * 256;          // 0..16383 float4s
                    int r   = idx >> 9;               // 512 float4 per pixel row
                    int c4  = idx & 511;
                    __stcs((float4*)(out + ((size_t)(bi * 32 + r) * HW + bj * 32) * 64) + c4, z);
                }
            }
        }
    }
}

// ====================== launch =================================
extern "C" void kernel_launch(void* const* d_in, const int* in_sizes, int n_in,
                              void* d_out, int out_size) {
    const float* inp   = (const float*)d_in[0];
    const float* w     = (const float*)d_in[1];
    const float* cb    = (const float*)d_in[2];
    const float* gamma = (const float*)d_in[3];
    const float* beta  = (const float*)d_in[4];
    const float* mean  = (const float*)d_in[5];
    const float* var   = (const float*)d_in[6];
    const int*   abi   = (const int*)d_in[7];
    float* out = (float*)d_out;

    cudaFuncSetAttribute(convk, cudaFuncAttributeMaxDynamicSharedMemorySize, S_TOTAL_B);

    prep1<<<36, 256>>>(w, cb, gamma, beta, mean, var);
    prep2<<<2, 256>>>(abi);
    convk<<<148, 256, S_TOTAL_B>>>(inp, abi, out);
}

// round 3
// speedup vs baseline: 1.3855x; 1.3855x over previous
#include <cuda_runtime.h>
#include <cstdint>
#include <cstddef>

// ====================== problem constants ======================
#define HW     1024
#define NCONV  2048          // 512 active blocks * 4 tiles (16x16 px)
#define NTOT   3072          // + 1024 zero-fill block items

// ====================== smem layout (float words) ==============
#define S_SCALE_W 0
#define S_BIAS_W  64
#define S_PATCH_W 128                 // 18*18*64 = 20736 words
#define S_BP_W    20864               // weights: 36864 words
#define S_TOTAL_B 230912              // 57728 words * 4B

// ====================== helpers ================================
__device__ __forceinline__ float to_tf32(float x) {
    uint32_t u;
    asm("cvt.rna.tf32.f32 %0, %1;" : "=r"(u) : "f"(x));
    return __uint_as_float(u);
}

__device__ __forceinline__ void mma8(float* c,
                                     uint32_t a0, uint32_t a1, uint32_t a2, uint32_t a3,
                                     uint32_t b0, uint32_t b1) {
    asm volatile(
        "mma.sync.aligned.m16n8k8.row.col.f32.tf32.tf32.f32 "
        "{%0,%1,%2,%3}, {%4,%5,%6,%7}, {%8,%9}, {%0,%1,%2,%3};"
        : "+f"(c[0]), "+f"(c[1]), "+f"(c[2]), "+f"(c[3])
        : "r"(a0), "r"(a1), "r"(a2), "r"(a3), "r"(b0), "r"(b1));
}

__device__ __forceinline__ void cp_async16(uint32_t dst_smem, const void* src, int src_sz) {
    asm volatile("cp.async.cg.shared.global [%0], [%1], 16, %2;"
                 :: "r"(dst_smem), "l"(src), "r"(src_sz) : "memory");
}
__device__ __forceinline__ void cp_async_commit_wait() {
    asm volatile("cp.async.commit_group;" ::: "memory");
    asm volatile("cp.async.wait_group 0;" ::: "memory");
}

// ====================== single fused persistent kernel =========
// 148 CTAs x 512 threads, 1 CTA/SM.
// items 0..2047   : conv tiles, 16x16 px => implicit GEMM M=256,N=64,K=576
// items 2048..3071: zero-fill of inactive 32x32 blocks (sorted-index binsearch)
__global__ void __launch_bounds__(512, 1)
convk(const float* __restrict__ inp,  const float* __restrict__ w,
      const float* __restrict__ cb,   const float* __restrict__ gm,
      const float* __restrict__ bt,   const float* __restrict__ mn,
      const float* __restrict__ vr,   const int* __restrict__ abi,
      float* __restrict__ out) {
    extern __shared__ float sm[];
    const int tid  = threadIdx.x;
    const int wid  = tid >> 5;
    const int lane = tid & 31;
    const int grp  = lane >> 2;      // 0..7
    const int q    = lane & 3;       // 0..3

    uint32_t smem_u32;
    asm("{ .reg .u64 t; cvta.to.shared.u64 t, %1; cvt.u32.u64 %0, t; }"
        : "=r"(smem_u32) : "l"((const void*)sm));
    const uint32_t patch_u32 = smem_u32 + S_PATCH_W * 4;

    // ---- per-CTA prep: pack weights (tf32-RNA, fragment order), scale/bias ----
    {
        float4* bp = (float4*)(sm + S_BP_W);
        #pragma unroll 2
        for (int idx = tid; idx < 9216; idx += 512) {
            int qq = idx & 3;
            int n  = (idx >> 2) & 63;
            int tp = idx >> 8;
            float v[4];
            #pragma unroll
            for (int j = 0; j < 4; j++) {
                int k = 16 * tp + qq + 4 * j;
                int tap = k >> 6, ci = k & 63;
                v[j] = to_tf32(w[(tap * 64 + ci) * 64 + n]);
            }
            bp[idx] = make_float4(v[0], v[1], v[2], v[3]);
        }
        if (tid < 64) {
            float s = gm[tid] * rsqrtf(vr[tid] + 1e-3f);
            sm[S_SCALE_W + tid] = s;
            sm[S_BIAS_W + tid]  = cb[tid] * s + bt[tid] - mn[tid] * s;
        }
    }

    const int rb    = (wid >> 1) * 2;    // warp's pixel-row base (2 rows)
    const int nbase = (wid & 1) * 32;    // warp's output-channel base

    for (int it = blockIdx.x; it < NTOT; it += gridDim.x) {
        if (it < NCONV) {
            // ================= conv tile =================
            const int b   = it >> 2;
            const int sub = it & 3;
            const int gr0 = abi[3 * b + 1] * 32 + (sub >> 1) * 16;
            const int gc0 = abi[3 * b + 2] * 32 + (sub & 1) * 16;

            __syncthreads();   // prev tile's readers done with patch

            // ---- cp.async 18x18x64 patch (raw f32; HW truncates to tf32) ----
            // channel swizzle: word ^= ((pcol&3)<<3)|(pcol&4)
            {
                #pragma unroll
                for (int u = 0; u < 11; u++) {
                    int f = tid + u * 512;
                    if (u == 10) f = 5120 + tid;          // tail 64
                    if (u < 10 || tid < 64) {
                        int prow = f / 288;
                        int rem  = f - prow * 288;
                        int pcol = rem >> 4, c4 = rem & 15;
                        int ir = gr0 - 1 + prow, ic = gc0 - 1 + pcol;
                        int ok = ((unsigned)ir < (unsigned)HW) & ((unsigned)ic < (unsigned)HW);
                        const float* src = inp + ((size_t)(ir & 1023) * HW + (ic & 1023)) * 64 + c4 * 4;
                        int sw = ((pcol & 3) << 3) | (pcol & 4);
                        uint32_t dst = patch_u32 +
                            (((prow * 18 + pcol) * 64 + ((c4 * 4) ^ sw)) << 2);
                        cp_async16(dst, src, ok ? 16 : 0);
                    }
                }
                cp_async_commit_wait();
            }
            __syncthreads();

            // ---- K loop: 36 k16-steps (K=576) ----
            float acc[2][4][4];
            #pragma unroll
            for (int a = 0; a < 2; a++)
                #pragma unroll
                for (int c = 0; c < 4; c++)
                    #pragma unroll
                    for (int d = 0; d < 4; d++) acc[a][c][d] = 0.f;

            const float*  patch = sm + S_PATCH_W;
            const float4* bp    = (const float4*)(sm + S_BP_W);

            #pragma unroll 2
            for (int t2 = 0; t2 < 36; t2++) {
                const int tap = t2 >> 2;                       // 0..8
                const int kh  = (tap >= 6) ? 2 : (tap >= 3 ? 1 : 0);
                const int kw  = tap - kh * 3;

                float4 bf[4];
                #pragma unroll
                for (int nf = 0; nf < 4; nf++)
                    bf[nf] = bp[(t2 * 64 + nbase + nf * 8 + grp) * 4 + q];

                const int pc    = grp + kw;                    // 0..9
                const int sw    = ((pc & 3) << 3) | (pc & 4);
                const int cib0  = ((2 * t2) & 7) << 3;
                const int base0 = ((rb + kh) * 18 + pc) * 64;

                #pragma unroll
                for (int hv = 0; hv < 2; hv++) {
                    const int e0 = ((cib0 + hv * 8) + q) ^ sw;
                    const int e1 = e0 ^ 4;
                    #pragma unroll
                    for (int mf = 0; mf < 2; mf++) {
                        const int ba = base0 + mf * 1152;      // next pixel row
                        uint32_t a0 = __float_as_uint(patch[ba + e0]);
                        uint32_t a1 = __float_as_uint(patch[ba + 512 + e0]);
                        uint32_t a2 = __float_as_uint(patch[ba + e1]);
                        uint32_t a3 = __float_as_uint(patch[ba + 512 + e1]);
                        #pragma unroll
                        for (int nf = 0; nf < 4; nf++) {
                            uint32_t b0 = __float_as_uint(hv ? bf[nf].z : bf[nf].x);
                            uint32_t b1 = __float_as_uint(hv ? bf[nf].w : bf[nf].y);
                            mma8(acc[mf][nf], a0, a1, a2, a3, b0, b1);
                        }
                    }
                }
            }

            // ---- epilogue: fused BN scale/bias + ReLU ----
            #pragma unroll
            for (int mf = 0; mf < 2; mf++) {
                const int gpr = gr0 + rb + mf;
                #pragma unroll
                for (int nf = 0; nf < 4; nf++) {
                    const int n0 = nbase + nf * 8 + 2 * q;
                    const float s0 = sm[S_SCALE_W + n0], s1 = sm[S_SCALE_W + n0 + 1];
                    const float d0 = sm[S_BIAS_W + n0],  d1 = sm[S_BIAS_W + n0 + 1];
                    float* p0 = out + ((size_t)gpr * HW + gc0 + grp) * 64 + n0;
                    float2 v0, v1;
                    v0.x = fmaxf(fmaf(acc[mf][nf][0], s0, d0), 0.f);
                    v0.y = fmaxf(fmaf(acc[mf][nf][1], s1, d1), 0.f);
                    v1.x = fmaxf(fmaf(acc[mf][nf][2], s0, d0), 0.f);
                    v1.y = fmaxf(fmaf(acc[mf][nf][3], s1, d1), 0.f);
                    __stcs((float2*)p0, v0);
                    __stcs((float2*)(p0 + 8 * 64), v1);        // pixel col grp+8
                }
            }
        } else {
            // ================= zero-fill item =================
            const int blk = it - NCONV;
            // abi rows are sorted by flat = i*32+j (reference sorts) -> binsearch
            int lo = 0, hi = 511, found = 0;
            while (lo <= hi) {
                int mid = (lo + hi) >> 1;
                int f = abi[3 * mid + 1] * 32 + abi[3 * mid + 2];
                if (f == blk) { found = 1; break; }
                if (f < blk) lo = mid + 1; else hi = mid - 1;
            }
            if (!found) {
                const int bi = blk >> 5, bj = blk & 31;
                const float4 z = make_float4(0.f, 0.f, 0.f, 0.f);
                #pragma unroll 8
                for (int j = 0; j < 32; j++) {
                    int idx = tid + j * 512;          // 0..16383 float4s
                    int r   = idx >> 9;               // 512 float4 per pixel row
                    int c4  = idx & 511;
                    __stcs((float4*)(out + ((size_t)(bi * 32 + r) * HW + bj * 32) * 64) + c4, z);
                }
            }
        }
    }
}

// ====================== launch =================================
extern "C" void kernel_launch(void* const* d_in, const int* in_sizes, int n_in,
                              void* d_out, int out_size) {
    const float* inp   = (const float*)d_in[0];
    const float* w     = (const float*)d_in[1];
    const float* cb    = (const float*)d_in[2];
    const float* gamma = (const float*)d_in[3];
    const float* beta  = (const float*)d_in[4];
    const float* mean  = (const float*)d_in[5];
    const float* var   = (const float*)d_in[6];
    const int*   abi   = (const int*)d_in[7];
    float* out = (float*)d_out;

    cudaFuncSetAttribute(convk, cudaFuncAttributeMaxDynamicSharedMemorySize, S_TOTAL_B);
    convk<<<148, 512, S_TOTAL_B>>>(inp, w, cb, gamma, beta, mean, var, abi, out);
}

// round 4
// speedup vs baseline: 1.4093x; 1.0172x over previous
#include <cuda_runtime.h>
#include <cstdint>
#include <cstddef>

// ====================== problem constants ======================
#define HW     1024
#define NCONV  2048          // 512 active blocks * 4 tiles (16x16 px)
#define NTOT   3072          // + 1024 zero-fill block items

// ====================== smem layout (float words) ==============
#define S_SCALE_W 0
#define S_BIAS_W  64
#define S_PATCH_W 128                 // 18*18*64 = 20736 words
#define S_BP_W    20864               // weights: 36864 words
#define S_TOTAL_B 230912              // 57728 words * 4B

// ====================== helpers ================================
__device__ __forceinline__ float to_tf32(float x) {
    uint32_t u;
    asm("cvt.rna.tf32.f32 %0, %1;" : "=r"(u) : "f"(x));
    return __uint_as_float(u);
}

__device__ __forceinline__ void mma8(float* c,
                                     uint32_t a0, uint32_t a1, uint32_t a2, uint32_t a3,
                                     uint32_t b0, uint32_t b1) {
    asm volatile(
        "mma.sync.aligned.m16n8k8.row.col.f32.tf32.tf32.f32 "
        "{%0,%1,%2,%3}, {%4,%5,%6,%7}, {%8,%9}, {%0,%1,%2,%3};"
        : "+f"(c[0]), "+f"(c[1]), "+f"(c[2]), "+f"(c[3])
        : "r"(a0), "r"(a1), "r"(a2), "r"(a3), "r"(b0), "r"(b1));
}

__device__ __forceinline__ void cp_async16(uint32_t dst_smem, const void* src, int src_sz) {
    asm volatile("cp.async.cg.shared.global [%0], [%1], 16, %2;"
                 :: "r"(dst_smem), "l"(src), "r"(src_sz) : "memory");
}
__device__ __forceinline__ void cp_async_commit_wait() {
    asm volatile("cp.async.commit_group;" ::: "memory");
    asm volatile("cp.async.wait_group 0;" ::: "memory");
}

// One k16 step (two k8 mma steps) for warp tile 32m x 64n.
#define KSTEP(T2, BF)                                                       \
{                                                                           \
    const int tap_  = (T2) >> 2;                                            \
    const int kh_   = (tap_ >= 6) ? 2 : (tap_ >= 3 ? 1 : 0);                \
    const int kw_   = tap_ - kh_ * 3;                                       \
    const int pc_   = grp + kw_;                                            \
    const int sw_   = ((pc_ & 3) << 3) | (pc_ & 4);                         \
    const int cib0_ = (((T2) & 3) << 4);                                    \
    const int base0_ = ((rb + kh_) * 18 + pc_) * 64;                        \
    _Pragma("unroll")                                                       \
    for (int hv = 0; hv < 2; hv++) {                                        \
        const int e0 = ((cib0_ + hv * 8) + q) ^ sw_;                        \
        const int e1 = e0 ^ 4;                                              \
        _Pragma("unroll")                                                   \
        for (int mf = 0; mf < 2; mf++) {                                    \
            const int ba = base0_ + mf * 1152;                              \
            uint32_t a0 = __float_as_uint(patch[ba + e0]);                  \
            uint32_t a1 = __float_as_uint(patch[ba + 512 + e0]);            \
            uint32_t a2 = __float_as_uint(patch[ba + e1]);                  \
            uint32_t a3 = __float_as_uint(patch[ba + 512 + e1]);            \
            _Pragma("unroll")                                               \
            for (int nf = 0; nf < 8; nf++) {                                \
                uint32_t b0 = __float_as_uint(hv ? BF[nf].z : BF[nf].x);    \
                uint32_t b1 = __float_as_uint(hv ? BF[nf].w : BF[nf].y);    \
                mma8(acc[mf][nf], a0, a1, a2, a3, b0, b1);                  \
            }                                                               \
        }                                                                   \
    }                                                                       \
}

// ====================== single fused persistent kernel =========
// 148 CTAs x 256 threads (8 warps), 1 CTA/SM.
// Warp tile: 32 m-rows (2 pixel rows x 16 cols) x 64 n (all output channels).
__global__ void __launch_bounds__(256, 1)
convk(const float* __restrict__ inp,  const float* __restrict__ w,
      const float* __restrict__ cb,   const float* __restrict__ gm,
      const float* __restrict__ bt,   const float* __restrict__ mn,
      const float* __restrict__ vr,   const int* __restrict__ abi,
      float* __restrict__ out) {
    extern __shared__ float sm[];
    const int tid  = threadIdx.x;
    const int wid  = tid >> 5;
    const int lane = tid & 31;
    const int grp  = lane >> 2;      // 0..7
    const int q    = lane & 3;       // 0..3

    uint32_t smem_u32;
    asm("{ .reg .u64 t; cvta.to.shared.u64 t, %1; cvt.u32.u64 %0, t; }"
        : "=r"(smem_u32) : "l"((const void*)sm));
    const uint32_t patch_u32 = smem_u32 + S_PATCH_W * 4;

    // ---- per-CTA prep: pack weights (tf32-RNA, fragment order), scale/bias ----
    {
        float4* bpw = (float4*)(sm + S_BP_W);
        #pragma unroll 2
        for (int idx = tid; idx < 9216; idx += 256) {
            int qq = idx & 3;
            int n  = (idx >> 2) & 63;
            int tp = idx >> 8;
            float v[4];
            #pragma unroll
            for (int j = 0; j < 4; j++) {
                int k = 16 * tp + qq + 4 * j;
                int tap = k >> 6, ci = k & 63;
                v[j] = to_tf32(w[(tap * 64 + ci) * 64 + n]);
            }
            bpw[idx] = make_float4(v[0], v[1], v[2], v[3]);
        }
        if (tid < 64) {
            float s = gm[tid] * rsqrtf(vr[tid] + 1e-3f);
            sm[S_SCALE_W + tid] = s;
            sm[S_BIAS_W + tid]  = cb[tid] * s + bt[tid] - mn[tid] * s;
        }
    }

    const int rb = wid * 2;              // warp's pixel-row base (2 rows)

    for (int it = blockIdx.x; it < NTOT; it += gridDim.x) {
        if (it < NCONV) {
            // ================= conv tile =================
            const int b   = it >> 2;
            const int sub = it & 3;
            const int gr0 = abi[3 * b + 1] * 32 + (sub >> 1) * 16;
            const int gc0 = abi[3 * b + 2] * 32 + (sub & 1) * 16;

            __syncthreads();   // prev tile's readers done with patch

            // ---- cp.async 18x18x64 patch (raw f32; HW truncates to tf32) ----
            {
                #pragma unroll
                for (int u = 0; u < 21; u++) {
                    int f = tid + u * 256;
                    if (u < 20 || tid < 64) {
                        int prow = f / 288;
                        int rem  = f - prow * 288;
                        int pcol = rem >> 4, c4 = rem & 15;
                        int ir = gr0 - 1 + prow, ic = gc0 - 1 + pcol;
                        int ok = ((unsigned)ir < (unsigned)HW) & ((unsigned)ic < (unsigned)HW);
                        const float* src = inp + ((size_t)(ir & 1023) * HW + (ic & 1023)) * 64 + c4 * 4;
                        int sw = ((pcol & 3) << 3) | (pcol & 4);
                        uint32_t dst = patch_u32 +
                            (((prow * 18 + pcol) * 64 + ((c4 * 4) ^ sw)) << 2);
                        cp_async16(dst, src, ok ? 16 : 0);
                    }
                }
                cp_async_commit_wait();
            }
            __syncthreads();

            // ---- K loop: 36 k16-steps, B frags double-buffered in regs ----
            float acc[2][8][4];
            #pragma unroll
            for (int a = 0; a < 2; a++)
                #pragma unroll
                for (int c = 0; c < 8; c++)
                    #pragma unroll
                    for (int d = 0; d < 4; d++) acc[a][c][d] = 0.f;

            const float*  patch = sm + S_PATCH_W;
            const float4* bp    = (const float4*)(sm + S_BP_W);

            float4 bfa[8], bfb[8];
            #pragma unroll
            for (int nf = 0; nf < 8; nf++)
                bfa[nf] = bp[(nf * 8 + grp) * 4 + q];

            #pragma unroll 1
            for (int tt = 0; tt < 18; tt++) {
                const int t2 = 2 * tt;
                #pragma unroll
                for (int nf = 0; nf < 8; nf++)
                    bfb[nf] = bp[((t2 + 1) * 64 + nf * 8 + grp) * 4 + q];
                KSTEP(t2, bfa);
                const int t2n = (tt < 17) ? (t2 + 2) : 0;
                #pragma unroll
                for (int nf = 0; nf < 8; nf++)
                    bfa[nf] = bp[(t2n * 64 + nf * 8 + grp) * 4 + q];
                KSTEP(t2 + 1, bfb);
            }

            // ---- epilogue: fused BN scale/bias + ReLU ----
            #pragma unroll
            for (int mf = 0; mf < 2; mf++) {
                const int gpr = gr0 + rb + mf;
                #pragma unroll
                for (int nf = 0; nf < 8; nf++) {
                    const int n0 = nf * 8 + 2 * q;
                    const float s0 = sm[S_SCALE_W + n0], s1 = sm[S_SCALE_W + n0 + 1];
                    const float d0 = sm[S_BIAS_W + n0],  d1 = sm[S_BIAS_W + n0 + 1];
                    float* p0 = out + ((size_t)gpr * HW + gc0 + grp) * 64 + n0;
                    float2 v0, v1;
                    v0.x = fmaxf(fmaf(acc[mf][nf][0], s0, d0), 0.f);
                    v0.y = fmaxf(fmaf(acc[mf][nf][1], s1, d1), 0.f);
                    v1.x = fmaxf(fmaf(acc[mf][nf][2], s0, d0), 0.f);
                    v1.y = fmaxf(fmaf(acc[mf][nf][3], s1, d1), 0.f);
                    __stcs((float2*)p0, v0);
                    __stcs((float2*)(p0 + 8 * 64), v1);        // pixel col grp+8
                }
            }
        } else {
            // ================= zero-fill item =================
            const int blk = it - NCONV;
            // abi rows sorted by flat = i*32+j -> binary search
            int lo = 0, hi = 511, found = 0;
            while (lo <= hi) {
                int mid = (lo + hi) >> 1;
                int f = abi[3 * mid + 1] * 32 + abi[3 * mid + 2];
                if (f == blk) { found = 1; break; }
                if (f < blk) lo = mid + 1; else hi = mid - 1;
            }
            if (!found) {
                const int bi = blk >> 5, bj = blk & 31;
                const float4 z = make_float4(0.f, 0.f, 0.f, 0.f);
                #pragma unroll 8
                for (int j = 0; j < 64; j++) {
                    int idx = tid + j * 256;          // 0..16383 float4s
                    int r   = idx >> 9;               // 512 float4 per pixel row
                    int c4  = idx & 511;
                    __stcs((float4*)(out + ((size_t)(bi * 32 + r) * HW + bj * 32) * 64) + c4, z);
                }
            }
        }
    }
}

// ====================== launch =================================
extern "C" void kernel_launch(void* const* d_in, const int* in_sizes, int n_in,
                              void* d_out, int out_size) {
    const float* inp   = (const float*)d_in[0];
    const float* w     = (const float*)d_in[1];
    const float* cb    = (const float*)d_in[2];
    const float* gamma = (const float*)d_in[3];
    const float* beta  = (const float*)d_in[4];
    const float* mean  = (const float*)d_in[5];
    const float* var   = (const float*)d_in[6];
    const int*   abi   = (const int*)d_in[7];
    float* out = (float*)d_out;

    cudaFuncSetAttribute(convk, cudaFuncAttributeMaxDynamicSharedMemorySize, S_TOTAL_B);
    convk<<<148, 256, S_TOTAL_B>>>(inp, w, cb, gamma, beta, mean, var, abi, out);
}

// round 5
// speedup vs baseline: 1.5207x; 1.0791x over previous
#include <cuda_runtime.h>
#include <cstdint>
#include <cstddef>

// ====================== problem constants ======================
#define HW     1024
#define NCONV  2048          // 512 active blocks * 4 tiles (16x16 px)
#define NTOT   3072          // + 1024 zero-fill block items

// ====================== smem layout (float words) ==============
#define S_SCALE_W 0
#define S_BIAS_W  64
#define S_P0_W    128                 // half-patch 18*18*32 = 10368 words
#define S_P1_W    10496               // second half-patch buffer
#define S_BP_W    20864               // weights: 36864 words
#define S_TOTAL_B 230912              // 57728 words * 4B

// ====================== helpers ================================
__device__ __forceinline__ float to_tf32(float x) {
    uint32_t u;
    asm("cvt.rna.tf32.f32 %0, %1;" : "=r"(u) : "f"(x));
    return __uint_as_float(u);
}

__device__ __forceinline__ void mma8(float* c,
                                     uint32_t a0, uint32_t a1, uint32_t a2, uint32_t a3,
                                     uint32_t b0, uint32_t b1) {
    asm volatile(
        "mma.sync.aligned.m16n8k8.row.col.f32.tf32.tf32.f32 "
        "{%0,%1,%2,%3}, {%4,%5,%6,%7}, {%8,%9}, {%0,%1,%2,%3};"
        : "+f"(c[0]), "+f"(c[1]), "+f"(c[2]), "+f"(c[3])
        : "r"(a0), "r"(a1), "r"(a2), "r"(a3), "r"(b0), "r"(b1));
}

__device__ __forceinline__ void cp_async16(uint32_t dst_smem, const void* src, int src_sz) {
    asm volatile("cp.async.cg.shared.global [%0], [%1], 16, %2;"
                 :: "r"(dst_smem), "l"(src), "r"(src_sz) : "memory");
}
__device__ __forceinline__ void cp_commit() {
    asm volatile("cp.async.commit_group;" ::: "memory");
}
__device__ __forceinline__ void cp_wait1() {
    asm volatile("cp.async.wait_group 1;" ::: "memory");
}

// Issue cp.async loads of half h (channels 32h..32h+31) of an 18x18 patch
// around (gr0-1, gc0-1) into the half-buffer at smem byte address dstb.
// Swizzle: word ci' = ci ^ ((pcol&7)<<2)  -> conflict-free A frags & STS.
__device__ __forceinline__ void issue_half(const float* __restrict__ inp,
                                           int gr0, int gc0, int h,
                                           uint32_t dstb, int tid) {
    #pragma unroll
    for (int u = 0; u < 11; u++) {
        int f = tid + u * 256;
        if (u == 10) f = 2560 + tid;       // tail: 32 float4
        if (u < 10 || tid < 32) {
            int prow = f / 144;
            int rem  = f - prow * 144;
            int pcol = rem >> 3, c8 = rem & 7;
            int ir = gr0 - 1 + prow, ic = gc0 - 1 + pcol;
            int ok = ((unsigned)ir < (unsigned)HW) & ((unsigned)ic < (unsigned)HW);
            const float* src = inp + ((size_t)(ir & 1023) * HW + (ic & 1023)) * 64
                               + h * 32 + c8 * 4;
            int swz = (pcol & 7) << 2;
            uint32_t dst = dstb + (((((prow * 18 + pcol) << 5) + ((c8 * 4) ^ swz))) << 2);
            cp_async16(dst, src, ok ? 16 : 0);
        }
    }
}

// One k16 step (two k8 mmas) inside a half-buffer. SS=tap 0..8, J=0/1 selects
// the 16-channel group within the half. Warp tile 32m x 64n.
#define KSTEP_H(SS, J, BF, PW)                                              \
{                                                                           \
    const int kh_ = ((SS) >= 6) ? 2 : (((SS) >= 3) ? 1 : 0);                \
    const int kw_ = (SS) - kh_ * 3;                                         \
    const int pc_ = grp + kw_;                                              \
    const int swz_ = (pc_ & 7) << 2;                                        \
    const int base0_ = ((rb + kh_) * 18 + pc_) << 5;                        \
    _Pragma("unroll")                                                       \
    for (int hv = 0; hv < 2; hv++) {                                        \
        const int e0 = (((J) << 4) + hv * 8 + q) ^ swz_;                    \
        const int e1 = e0 ^ 4;                                              \
        _Pragma("unroll")                                                   \
        for (int mf = 0; mf < 2; mf++) {                                    \
            const int ba = base0_ + mf * 576;                               \
            uint32_t a0 = __float_as_uint((PW)[ba + e0]);                   \
            uint32_t a1 = __float_as_uint((PW)[ba + 256 + e0]);             \
            uint32_t a2 = __float_as_uint((PW)[ba + e1]);                   \
            uint32_t a3 = __float_as_uint((PW)[ba + 256 + e1]);             \
            _Pragma("unroll")                                               \
            for (int nf = 0; nf < 8; nf++) {                                \
                uint32_t b0 = __float_as_uint(hv ? BF[nf].z : BF[nf].x);    \
                uint32_t b1 = __float_as_uint(hv ? BF[nf].w : BF[nf].y);    \
                mma8(acc[mf][nf], a0, a1, a2, a3, b0, b1);                  \
            }                                                               \
        }                                                                   \
    }                                                                       \
}

// 18 k16-steps of one half (TB = 2*h), B frags reg-ping-ponged from smem.
#define COMPUTE_HALF(PWORD, TB)                                             \
{                                                                           \
    const float* pw = sm + (PWORD);                                         \
    float4 bfa[8], bfb[8];                                                  \
    _Pragma("unroll")                                                       \
    for (int nf = 0; nf < 8; nf++)                                          \
        bfa[nf] = bp[((TB) * 64 + nf * 8 + grp) * 4 + q];                   \
    _Pragma("unroll 1")                                                     \
    for (int ss = 0; ss < 9; ss++) {                                        \
        const int t2b = ss * 4 + (TB);                                      \
        _Pragma("unroll")                                                   \
        for (int nf = 0; nf < 8; nf++)                                      \
            bfb[nf] = bp[((t2b + 1) * 64 + nf * 8 + grp) * 4 + q];          \
        KSTEP_H(ss, 0, bfa, pw);                                            \
        const int t2n = (ss < 8) ? (t2b + 4) : (TB);                        \
        _Pragma("unroll")                                                   \
        for (int nf = 0; nf < 8; nf++)                                      \
            bfa[nf] = bp[(t2n * 64 + nf * 8 + grp) * 4 + q];                \
        KSTEP_H(ss, 1, bfb, pw);                                            \
    }                                                                       \
}

// ====================== single fused persistent kernel =========
// 148 CTAs x 256 threads (8 warps), 1 CTA/SM.
// Double-buffered ci-half patches: loads fully overlap the K loop.
__global__ void __launch_bounds__(256, 1)
convk(const float* __restrict__ inp,  const float* __restrict__ w,
      const float* __restrict__ cb,   const float* __restrict__ gm,
      const float* __restrict__ bt,   const float* __restrict__ mn,
      const float* __restrict__ vr,   const int* __restrict__ abi,
      float* __restrict__ out) {
    extern __shared__ float sm[];
    const int tid  = threadIdx.x;
    const int wid  = tid >> 5;
    const int lane = tid & 31;
    const int grp  = lane >> 2;      // 0..7
    const int q    = lane & 3;       // 0..3

    uint32_t smem_u32;
    asm("{ .reg .u64 t; cvta.to.shared.u64 t, %1; cvt.u32.u64 %0, t; }"
        : "=r"(smem_u32) : "l"((const void*)sm));
    const uint32_t p0_u32 = smem_u32 + S_P0_W * 4;
    const uint32_t p1_u32 = smem_u32 + S_P1_W * 4;

    // ---- per-CTA prep: pack weights (tf32-RNA, fragment order), scale/bias ----
    {
        float4* bpw = (float4*)(sm + S_BP_W);
        #pragma unroll 2
        for (int idx = tid; idx < 9216; idx += 256) {
            int qq = idx & 3;
            int n  = (idx >> 2) & 63;
            int tp = idx >> 8;
            float v[4];
            #pragma unroll
            for (int j = 0; j < 4; j++) {
                int k = 16 * tp + qq + 4 * j;
                int tap = k >> 6, ci = k & 63;
                v[j] = to_tf32(w[(tap * 64 + ci) * 64 + n]);
            }
            bpw[idx] = make_float4(v[0], v[1], v[2], v[3]);
        }
        if (tid < 64) {
            float s = gm[tid] * rsqrtf(vr[tid] + 1e-3f);
            sm[S_SCALE_W + tid] = s;
            sm[S_BIAS_W + tid]  = cb[tid] * s + bt[tid] - mn[tid] * s;
        }
    }

    const int rb = wid * 2;              // warp's pixel-row base (2 rows)
    const float4* bp = (const float4*)(sm + S_BP_W);

    // ---- prologue: start loading first tile's half0 ----
    int gr0, gc0;
    {
        const int it0 = blockIdx.x;      // always < NCONV (148 < 2048)
        const int b = it0 >> 2, sub = it0 & 3;
        gr0 = abi[3 * b + 1] * 32 + (sub >> 1) * 16;
        gc0 = abi[3 * b + 2] * 32 + (sub & 1) * 16;
        issue_half(inp, gr0, gc0, 0, p0_u32, tid);
        cp_commit();
    }

    for (int it = blockIdx.x; it < NTOT; it += gridDim.x) {
        if (it < NCONV) {
            // ---- start half1 load, then compute half0 ----
            issue_half(inp, gr0, gc0, 1, p1_u32, tid);
            cp_commit();
            cp_wait1();                  // half0 ready (half1 in flight)
            __syncthreads();

            float acc[2][8][4];
            #pragma unroll
            for (int a = 0; a < 2; a++)
                #pragma unroll
                for (int c = 0; c < 8; c++)
                    #pragma unroll
                    for (int d = 0; d < 4; d++) acc[a][c][d] = 0.f;

            COMPUTE_HALF(S_P0_W, 0)
            __syncthreads();             // all warps done reading P0

            // ---- start next tile's half0 load, then compute half1 ----
            const int itn = it + gridDim.x;
            int grn = 0, gcn = 0;
            if (itn < NCONV) {
                const int b = itn >> 2, sub = itn & 3;
                grn = abi[3 * b + 1] * 32 + (sub >> 1) * 16;
                gcn = abi[3 * b + 2] * 32 + (sub & 1) * 16;
                issue_half(inp, grn, gcn, 0, p0_u32, tid);
            }
            cp_commit();
            cp_wait1();                  // half1 ready (next-h0 in flight)
            __syncthreads();

            COMPUTE_HALF(S_P1_W, 2)

            // ---- epilogue: fused BN scale/bias + ReLU ----
            #pragma unroll
            for (int mf = 0; mf < 2; mf++) {
                const int gpr = gr0 + rb + mf;
                #pragma unroll
                for (int nf = 0; nf < 8; nf++) {
                    const int n0 = nf * 8 + 2 * q;
                    const float s0 = sm[S_SCALE_W + n0], s1 = sm[S_SCALE_W + n0 + 1];
                    const float d0 = sm[S_BIAS_W + n0],  d1 = sm[S_BIAS_W + n0 + 1];
                    float* p0 = out + ((size_t)gpr * HW + gc0 + grp) * 64 + n0;
                    float2 v0, v1;
                    v0.x = fmaxf(fmaf(acc[mf][nf][0], s0, d0), 0.f);
                    v0.y = fmaxf(fmaf(acc[mf][nf][1], s1, d1), 0.f);
                    v1.x = fmaxf(fmaf(acc[mf][nf][2], s0, d0), 0.f);
                    v1.y = fmaxf(fmaf(acc[mf][nf][3], s1, d1), 0.f);
                    __stcs((float2*)p0, v0);
                    __stcs((float2*)(p0 + 8 * 64), v1);        // pixel col grp+8
                }
            }
            __syncthreads();             // P1 free for next iter's issue
            gr0 = grn; gc0 = gcn;
        } else {
            // ================= zero-fill item =================
            const int blk = it - NCONV;
            // abi rows sorted by flat = i*32+j -> binary search
            int lo = 0, hi = 511, found = 0;
            while (lo <= hi) {
                int mid = (lo + hi) >> 1;
                int f = abi[3 * mid + 1] * 32 + abi[3 * mid + 2];
                if (f == blk) { found = 1; break; }
                if (f < blk) lo = mid + 1; else hi = mid - 1;
            }
            if (!found) {
                const int bi = blk >> 5, bj = blk & 31;
                const float4 z = make_float4(0.f, 0.f, 0.f, 0.f);
                #pragma unroll 8
                for (int j = 0; j < 64; j++) {
                    int idx = tid + j * 256;          // 0..16383 float4s
                    int r   = idx >> 9;               // 512 float4 per pixel row
                    int c4  = idx & 511;
                    __stcs((float4*)(out + ((size_t)(bi * 32 + r) * HW + bj * 32) * 64) + c4, z);
                }
            }
        }
    }
}

// ====================== launch =================================
extern "C" void kernel_launch(void* const* d_in, const int* in_sizes, int n_in,
                              void* d_out, int out_size) {
    const float* inp   = (const float*)d_in[0];
    const float* w     = (const float*)d_in[1];
    const float* cb    = (const float*)d_in[2];
    const float* gamma = (const float*)d_in[3];
    const float* beta  = (const float*)d_in[4];
    const float* mean  = (const float*)d_in[5];
    const float* var   = (const float*)d_in[6];
    const int*   abi   = (const int*)d_in[7];
    float* out = (float*)d_out;

    cudaFuncSetAttribute(convk, cudaFuncAttributeMaxDynamicSharedMemorySize, S_TOTAL_B);
    convk<<<148, 256, S_TOTAL_B>>>(inp, w, cb, gamma, beta, mean, var, abi, out);
}

// round 6
// speedup vs baseline: 2.1387x; 1.4064x over previous
#include <cuda_runtime.h>
#include <cuda_fp16.h>
#include <cstdint>
#include <cstddef>

// ====================== problem constants ======================
#define HW     1024
#define NCONV  2048          // 512 active blocks * 4 tiles (16x16 px)
#define NTOT   3072          // + 1024 zero-fill block items

// ====================== smem layout (32-bit words) =============
#define S_SCALE_W 0
#define S_BIAS_W  64
#define S_ST0_W   128                 // f32 stage half: 18*18*32 = 10368 words
#define S_ST1_W   10496
#define S_F0_W    20864               // fp16 half: 18*18*16 = 5184 words
#define S_F1_W    26048
#define S_WP_W    31232               // fp16 weights: 9216 uint2 = 18432 words
#define S_TOTAL_B 198656              // 49664 words * 4B

// ====================== helpers ================================
__device__ __forceinline__ void mma16(float* c,
                                      uint32_t a0, uint32_t a1, uint32_t a2, uint32_t a3,
                                      uint32_t b0, uint32_t b1) {
    asm volatile(
        "mma.sync.aligned.m16n8k16.row.col.f32.f16.f16.f32 "
        "{%0,%1,%2,%3}, {%4,%5,%6,%7}, {%8,%9}, {%0,%1,%2,%3};"
        : "+f"(c[0]), "+f"(c[1]), "+f"(c[2]), "+f"(c[3])
        : "r"(a0), "r"(a1), "r"(a2), "r"(a3), "r"(b0), "r"(b1));
}

__device__ __forceinline__ uint32_t pack_h2(float lo, float hi) {
    __half2 h = __floats2half2_rn(lo, hi);
    return *(uint32_t*)&h;
}

__device__ __forceinline__ void cp_async16(uint32_t dst_smem, const void* src, int src_sz) {
    asm volatile("cp.async.cg.shared.global [%0], [%1], 16, %2;"
                 :: "r"(dst_smem), "l"(src), "r"(src_sz) : "memory");
}
__device__ __forceinline__ void cp_commit() {
    asm volatile("cp.async.commit_group;" ::: "memory");
}
__device__ __forceinline__ void cp_wait1() {
    asm volatile("cp.async.wait_group 1;" ::: "memory");
}
__device__ __forceinline__ void cp_wait0() {
    asm volatile("cp.async.wait_group 0;" ::: "memory");
}

// Issue cp.async of half h (channels 32h..32h+31) of the 18x18 patch around
// (gr0-1, gc0-1) into a LINEAR f32 stage buffer at smem byte address dstb.
__device__ __forceinline__ void issue_half(const float* __restrict__ inp,
                                           int gr0, int gc0, int h,
                                           uint32_t dstb, int tid) {
    #pragma unroll
    for (int u = 0; u < 11; u++) {
        int f = tid + u * 256;
        if (u == 10) f = 2560 + tid;          // tail: 32 float4
        if (u < 10 || tid < 32) {
            int prow = f / 144;
            int rem  = f - prow * 144;
            int pcol = rem >> 3, c8 = rem & 7;
            int ir = gr0 - 1 + prow, ic = gc0 - 1 + pcol;
            int ok = ((unsigned)ir < (unsigned)HW) & ((unsigned)ic < (unsigned)HW);
            const float* src = inp + ((size_t)(ir & 1023) * HW + (ic & 1023)) * 64
                               + h * 32 + c8 * 4;
            cp_async16(dstb + f * 16, src, ok ? 16 : 0);
        }
    }
}

// Convert one staged f32 half -> fp16 half with swizzle cw ^= ((pcol>>1)&3)<<2.
// fp16 layout: word index = pix*16 + cw, word = half2(ch 2cw, ch 2cw+1).
__device__ __forceinline__ void convert_half(const float* __restrict__ stg,
                                             uint32_t* __restrict__ dst, int tid) {
    #pragma unroll
    for (int u = 0; u < 11; u++) {
        int f = tid + u * 256;
        if (u == 10) f = 2560 + tid;
        if (u < 10 || tid < 32) {
            float4 v = ((const float4*)stg)[f];
            int pix  = f >> 3, c8 = f & 7;
            int pcol = pix % 18;
            int swz  = ((pcol >> 1) & 3) << 2;
            uint2 o;
            o.x = pack_h2(v.x, v.y);
            o.y = pack_h2(v.z, v.w);
            *(uint2*)(dst + pix * 16 + ((c8 * 2) ^ swz)) = o;
        }
    }
}

// One k16 mma step: tap SS (0..8), 16-ch group CIG (0/1) within the half.
// Warp tile 32m (2 pixel rows x 16 cols) x 64n.
#define KSTEP16(SS, CIG, BF, PW)                                            \
{                                                                           \
    const int kh_ = ((SS) >= 6) ? 2 : (((SS) >= 3) ? 1 : 0);                \
    const int kw_ = (SS) - kh_ * 3;                                         \
    const int pc_ = grp + kw_;                                              \
    const int swz_ = ((pc_ >> 1) & 3) << 2;                                 \
    const int e0 = (((CIG) << 3) + q) ^ swz_;                               \
    const int e2 = e0 ^ 4;                                                  \
    _Pragma("unroll")                                                       \
    for (int mf = 0; mf < 2; mf++) {                                        \
        const int ba = ((rb + mf + kh_) * 18 + pc_) << 4;                   \
        uint32_t a0 = (PW)[ba + e0];                                        \
        uint32_t a1 = (PW)[ba + 128 + e0];                                  \
        uint32_t a2 = (PW)[ba + e2];                                        \
        uint32_t a3 = (PW)[ba + 128 + e2];                                  \
        _Pragma("unroll")                                                   \
        for (int nf = 0; nf < 8; nf++)                                      \
            mma16(acc[mf][nf], a0, a1, a2, a3, BF[nf].x, BF[nf].y);         \
    }                                                                       \
}

// 18 k16-steps of one ci-half (H = 0/1), B frags reg-ping-ponged.
// weight step index t = tap*4 + H*2 + cig.
#define COMPUTE_HALF16(FW, H)                                               \
{                                                                           \
    const uint32_t* pw = (const uint32_t*)(sm + (FW));                      \
    const int tb0 = (H) * 2;                                                \
    uint2 bfa[8], bfb[8];                                                   \
    _Pragma("unroll")                                                       \
    for (int nf = 0; nf < 8; nf++)                                          \
        bfa[nf] = bp2[(tb0 * 64 + nf * 8 + grp) * 4 + q];                   \
    _Pragma("unroll 1")                                                     \
    for (int ss = 0; ss < 9; ss++) {                                        \
        const int tA = ss * 4 + tb0;                                        \
        _Pragma("unroll")                                                   \
        for (int nf = 0; nf < 8; nf++)                                      \
            bfb[nf] = bp2[((tA + 1) * 64 + nf * 8 + grp) * 4 + q];          \
        KSTEP16(ss, 0, bfa, pw);                                            \
        const int tn = (ss < 8) ? (tA + 4) : tb0;                           \
        _Pragma("unroll")                                                   \
        for (int nf = 0; nf < 8; nf++)                                      \
            bfa[nf] = bp2[(tn * 64 + nf * 8 + grp) * 4 + q];                \
        KSTEP16(ss, 1, bfb, pw);                                            \
    }                                                                       \
}

// ====================== single fused persistent kernel =========
// 148 CTAs x 256 threads (8 warps), 1 CTA/SM. fp16 mma, f32 accumulate.
__global__ void __launch_bounds__(256, 1)
convk(const float* __restrict__ inp,  const float* __restrict__ w,
      const float* __restrict__ cb,   const float* __restrict__ gm,
      const float* __restrict__ bt,   const float* __restrict__ mn,
      const float* __restrict__ vr,   const int* __restrict__ abi,
      float* __restrict__ out) {
    extern __shared__ float sm[];
    const int tid  = threadIdx.x;
    const int wid  = tid >> 5;
    const int lane = tid & 31;
    const int grp  = lane >> 2;      // 0..7
    const int q    = lane & 3;       // 0..3

    uint32_t smem_u32;
    asm("{ .reg .u64 t; cvta.to.shared.u64 t, %1; cvt.u32.u64 %0, t; }"
        : "=r"(smem_u32) : "l"((const void*)sm));
    const uint32_t st0_u32 = smem_u32 + S_ST0_W * 4;
    const uint32_t st1_u32 = smem_u32 + S_ST1_W * 4;

    // ---- per-CTA prep: fp16 weight fragments + fused scale/bias ----
    // wsm[(t*64 + n)*4 + q] = uint2{ h2(W[16t+2q][n],  W[16t+2q+1][n]),
    //                                h2(W[16t+2q+8][n],W[16t+2q+9][n]) }
    // where W[k][n] = conv_w linear (k = tap*64+ci).
    {
        uint2* wsm = (uint2*)(sm + S_WP_W);
        #pragma unroll 4
        for (int idx = tid; idx < 9216; idx += 256) {
            int qq = idx & 3;
            int n  = (idx >> 2) & 63;
            int t  = idx >> 8;
            int k0 = 16 * t + 2 * qq;
            uint2 o;
            o.x = pack_h2(w[k0 * 64 + n],       w[(k0 + 1) * 64 + n]);
            o.y = pack_h2(w[(k0 + 8) * 64 + n], w[(k0 + 9) * 64 + n]);
            wsm[idx] = o;
        }
        if (tid < 64) {
            float s = gm[tid] * rsqrtf(vr[tid] + 1e-3f);
            sm[S_SCALE_W + tid] = s;
            sm[S_BIAS_W + tid]  = cb[tid] * s + bt[tid] - mn[tid] * s;
        }
    }

    const int rb = wid * 2;              // warp's pixel-row base (2 rows)
    const uint2* bp2 = (const uint2*)(sm + S_WP_W);

    // ---- prologue: start loading first tile's half0 ----
    int gr0, gc0;
    {
        const int it0 = blockIdx.x;      // always < NCONV
        const int b = it0 >> 2, sub = it0 & 3;
        gr0 = abi[3 * b + 1] * 32 + (sub >> 1) * 16;
        gc0 = abi[3 * b + 2] * 32 + (sub & 1) * 16;
        issue_half(inp, gr0, gc0, 0, st0_u32, tid);
        cp_commit();
    }

    for (int it = blockIdx.x; it < NTOT; it += gridDim.x) {
        if (it < NCONV) {
            // ---- start half1 load; convert+compute half0 ----
            issue_half(inp, gr0, gc0, 1, st1_u32, tid);
            cp_commit();
            cp_wait1();                  // half0 staged (half1 in flight)
            __syncthreads();
            convert_half(sm + S_ST0_W, (uint32_t*)(sm + S_F0_W), tid);
            __syncthreads();

            float acc[2][8][4];
            #pragma unroll
            for (int a = 0; a < 2; a++)
                #pragma unroll
                for (int c = 0; c < 8; c++)
                    #pragma unroll
                    for (int d = 0; d < 4; d++) acc[a][c][d] = 0.f;

            COMPUTE_HALF16(S_F0_W, 0)

            // ---- start next tile's half0; convert+compute half1 ----
            const int itn = it + gridDim.x;
            int grn = 0, gcn = 0;
            if (itn < NCONV) {
                const int b = itn >> 2, sub = itn & 3;
                grn = abi[3 * b + 1] * 32 + (sub >> 1) * 16;
                gcn = abi[3 * b + 2] * 32 + (sub & 1) * 16;
                issue_half(inp, grn, gcn, 0, st0_u32, tid);
            }
            cp_commit();
            cp_wait1();                  // half1 staged (next-h0 in flight)
            __syncthreads();
            convert_half(sm + S_ST1_W, (uint32_t*)(sm + S_F1_W), tid);
            __syncthreads();

            COMPUTE_HALF16(S_F1_W, 1)

            // ---- epilogue: fused BN scale/bias + ReLU ----
            #pragma unroll
            for (int mf = 0; mf < 2; mf++) {
                const int gpr = gr0 + rb + mf;
                #pragma unroll
                for (int nf = 0; nf < 8; nf++) {
                    const int n0 = nf * 8 + 2 * q;
                    const float s0 = sm[S_SCALE_W + n0], s1 = sm[S_SCALE_W + n0 + 1];
                    const float d0 = sm[S_BIAS_W + n0],  d1 = sm[S_BIAS_W + n0 + 1];
                    float* p0 = out + ((size_t)gpr * HW + gc0 + grp) * 64 + n0;
                    float2 v0, v1;
                    v0.x = fmaxf(fmaf(acc[mf][nf][0], s0, d0), 0.f);
                    v0.y = fmaxf(fmaf(acc[mf][nf][1], s1, d1), 0.f);
                    v1.x = fmaxf(fmaf(acc[mf][nf][2], s0, d0), 0.f);
                    v1.y = fmaxf(fmaf(acc[mf][nf][3], s1, d1), 0.f);
                    __stcs((float2*)p0, v0);
                    __stcs((float2*)(p0 + 8 * 64), v1);        // pixel col grp+8
                }
            }
            __syncthreads();             // stage/f16 buffers free for next iter
            gr0 = grn; gc0 = gcn;
        } else {
            // ================= zero-fill item =================
            const int blk = it - NCONV;
            int lo = 0, hi = 511, found = 0;
            while (lo <= hi) {
                int mid = (lo + hi) >> 1;
                int f = abi[3 * mid + 1] * 32 + abi[3 * mid + 2];
                if (f == blk) { found = 1; break; }
                if (f < blk) lo = mid + 1; else hi = mid - 1;
            }
            if (!found) {
                const int bi = blk >> 5, bj = blk & 31;
                const float4 z = make_float4(0.f, 0.f, 0.f, 0.f);
                #pragma unroll 8
                for (int j = 0; j < 64; j++) {
                    int idx = tid + j * 256;          // 0..16383 float4s
                    int r   = idx >> 9;               // 512 float4 per pixel row
                    int c4  = idx & 511;
                    __stcs((float4*)(out + ((size_t)(bi * 32 + r) * HW + bj * 32) * 64) + c4, z);
                }
            }
        }
    }
    cp_wait0();                          // drain any in-flight cp.async
}

// ====================== launch =================================
extern "C" void kernel_launch(void* const* d_in, const int* in_sizes, int n_in,
                              void* d_out, int out_size) {
    const float* inp   = (const float*)d_in[0];
    const float* w     = (const float*)d_in[1];
    const float* cb    = (const float*)d_in[2];
    const float* gamma = (const float*)d_in[3];
    const float* beta  = (const float*)d_in[4];
    const float* mean  = (const float*)d_in[5];
    const float* var   = (const float*)d_in[6];
    const int*   abi   = (const int*)d_in[7];
    float* out = (float*)d_out;

    cudaFuncSetAttribute(convk, cudaFuncAttributeMaxDynamicSharedMemorySize, S_TOTAL_B);
    convk<<<148, 256, S_TOTAL_B>>>(inp, w, cb, gamma, beta, mean, var, abi, out);
}

// round 7
// speedup vs baseline: 2.2601x; 1.0568x over previous
#include <cuda_runtime.h>
#include <cuda_fp16.h>
#include <cstdint>
#include <cstddef>

// ====================== problem constants ======================
#define HW     1024
#define NCONV  1024          // 512 active blocks * 2 half-blocks (16 rows x 32 cols)
#define NTOT   2048          // + 1024 zero-fill block items

// ====================== smem layout (32-bit words) =============
#define S_SCALE_W 0
#define S_BIAS_W  64
#define S_STG_W   128                 // f32 stage: 18*34 px * 32 ch = 19584 words
#define S_F0_W    19712               // fp16 half: 18*34 px * 16 words = 9792
#define S_F1_W    29504
#define S_WP_W    39296               // fp16 weights: 9216 uint2 = 18432 words
#define S_TOTAL_B 230912              // 57728 words * 4B

// ====================== helpers ================================
__device__ __forceinline__ void mma16(float* c,
                                      uint32_t a0, uint32_t a1, uint32_t a2, uint32_t a3,
                                      uint32_t b0, uint32_t b1) {
    asm volatile(
        "mma.sync.aligned.m16n8k16.row.col.f32.f16.f16.f32 "
        "{%0,%1,%2,%3}, {%4,%5,%6,%7}, {%8,%9}, {%0,%1,%2,%3};"
        : "+f"(c[0]), "+f"(c[1]), "+f"(c[2]), "+f"(c[3])
        : "r"(a0), "r"(a1), "r"(a2), "r"(a3), "r"(b0), "r"(b1));
}

__device__ __forceinline__ uint32_t pack_h2(float lo, float hi) {
    __half2 h = __floats2half2_rn(lo, hi);
    return *(uint32_t*)&h;
}

__device__ __forceinline__ void cp_async16(uint32_t dst_smem, const void* src, int src_sz) {
    asm volatile("cp.async.cg.shared.global [%0], [%1], 16, %2;"
                 :: "r"(dst_smem), "l"(src), "r"(src_sz) : "memory");
}
__device__ __forceinline__ void cp_commit() {
    asm volatile("cp.async.commit_group;" ::: "memory");
}
__device__ __forceinline__ void cp_wait0() {
    asm volatile("cp.async.wait_group 0;" ::: "memory");
}

// Issue cp.async of ci-half h (channels 32h..32h+31) of the 18x34 patch around
// (gr0-1, gc0-1) into the LINEAR f32 stage buffer (byte address stgb).
// 18*34 px * 8 float4 = 4896 transfers.
__device__ __forceinline__ void issue_half(const float* __restrict__ inp,
                                           int gr0, int gc0, int h,
                                           uint32_t stgb, int tid) {
    #pragma unroll
    for (int u = 0; u < 20; u++) {
        int f = tid + u * 256;
        if (u < 19 || tid < 32) {
            int px = f >> 3, c8 = f & 7;
            int prow = px / 34;
            int pcol = px - prow * 34;
            int ir = gr0 - 1 + prow, ic = gc0 - 1 + pcol;
            int ok = ((unsigned)ir < (unsigned)HW) & ((unsigned)ic < (unsigned)HW);
            const float* src = inp + ((size_t)(ir & 1023) * HW + (ic & 1023)) * 64
                               + h * 32 + c8 * 4;
            cp_async16(stgb + f * 16, src, ok ? 16 : 0);
        }
    }
}

// Convert staged f32 half -> fp16 half. Swizzle cw ^= ((pcol>>1)&3)<<2.
// fp16 layout: word = px*16 + cw, word = half2(ch 2cw, ch 2cw+1).
__device__ __forceinline__ void convert_half(const float* __restrict__ stg,
                                             uint32_t* __restrict__ dst, int tid) {
    #pragma unroll
    for (int u = 0; u < 20; u++) {
        int f = tid + u * 256;
        if (u < 19 || tid < 32) {
            float4 v = ((const float4*)stg)[f];
            int px = f >> 3, c8 = f & 7;
            int pcol = px % 34;
            int swz = ((pcol >> 1) & 3) << 2;
            uint2 o;
            o.x = pack_h2(v.x, v.y);
            o.y = pack_h2(v.z, v.w);
            *(uint2*)(dst + px * 16 + ((c8 * 2) ^ swz)) = o;
        }
    }
}

// One k16 mma step: tap SS (0..8), 16-ch group CIG (0/1) within the half.
// Warp tile: 2 px rows x 32 px cols (64 m) x 64 n.
// mf: bit0 = px row, bit1 = col-half (cols 0..15 / 16..31).
#define KSTEP16(SS, CIG, BF, PW)                                            \
{                                                                           \
    const int kh_ = ((SS) >= 6) ? 2 : (((SS) >= 3) ? 1 : 0);                \
    const int kw_ = (SS) - kh_ * 3;                                         \
    _Pragma("unroll")                                                       \
    for (int mf = 0; mf < 4; mf++) {                                        \
        const int pc_ = grp + kw_ + ((mf >> 1) << 4);                       \
        const int swz_ = ((pc_ >> 1) & 3) << 2;                             \
        const int e0 = (((CIG) << 3) + q) ^ swz_;                           \
        const int e2 = e0 ^ 4;                                              \
        const int ba = ((rb + (mf & 1) + kh_) * 34 + pc_) << 4;             \
        uint32_t a0 = (PW)[ba + e0];                                        \
        uint32_t a1 = (PW)[ba + 128 + e0];                                  \
        uint32_t a2 = (PW)[ba + e2];                                        \
        uint32_t a3 = (PW)[ba + 128 + e2];                                  \
        _Pragma("unroll")                                                   \
        for (int nf = 0; nf < 8; nf++)                                      \
            mma16(acc[mf][nf], a0, a1, a2, a3, BF[nf].x, BF[nf].y);         \
    }                                                                       \
}

// 18 k16-steps of one ci-half (H = 0/1). Weight step t = tap*4 + H*2 + cig.
#define COMPUTE_HALF16(FW, H)                                               \
{                                                                           \
    const uint32_t* pw = (const uint32_t*)(sm + (FW));                      \
    const int tb0 = (H) * 2;                                                \
    uint2 bfa[8], bfb[8];                                                   \
    _Pragma("unroll")                                                       \
    for (int nf = 0; nf < 8; nf++)                                          \
        bfa[nf] = bp2[(tb0 * 64 + nf * 8 + grp) * 4 + q];                   \
    _Pragma("unroll 1")                                                     \
    for (int ss = 0; ss < 9; ss++) {                                        \
        const int tA = ss * 4 + tb0;                                        \
        _Pragma("unroll")                                                   \
        for (int nf = 0; nf < 8; nf++)                                      \
            bfb[nf] = bp2[((tA + 1) * 64 + nf * 8 + grp) * 4 + q];          \
        KSTEP16(ss, 0, bfa, pw);                                            \
        const int tn = (ss < 8) ? (tA + 4) : tb0;                           \
        _Pragma("unroll")                                                   \
        for (int nf = 0; nf < 8; nf++)                                      \
            bfa[nf] = bp2[(tn * 64 + nf * 8 + grp) * 4 + q];                \
        KSTEP16(ss, 1, bfb, pw);                                            \
    }                                                                       \
}

// ====================== single fused persistent kernel =========
// 148 CTAs x 256 threads (8 warps), 1 CTA/SM. fp16 mma, f32 accumulate.
// Item = half-block: M=512 (16 px rows x 32 cols), N=64, K=576.
__global__ void __launch_bounds__(256, 1)
convk(const float* __restrict__ inp,  const float* __restrict__ w,
      const float* __restrict__ cb,   const float* __restrict__ gm,
      const float* __restrict__ bt,   const float* __restrict__ mn,
      const float* __restrict__ vr,   const int* __restrict__ abi,
      float* __restrict__ out) {
    extern __shared__ float sm[];
    const int tid  = threadIdx.x;
    const int wid  = tid >> 5;
    const int lane = tid & 31;
    const int grp  = lane >> 2;      // 0..7
    const int q    = lane & 3;       // 0..3

    uint32_t smem_u32;
    asm("{ .reg .u64 t; cvta.to.shared.u64 t, %1; cvt.u32.u64 %0, t; }"
        : "=r"(smem_u32) : "l"((const void*)sm));
    const uint32_t stg_u32 = smem_u32 + S_STG_W * 4;

    // ---- per-CTA prep: fp16 weight fragments + fused scale/bias ----
    {
        uint2* wsm = (uint2*)(sm + S_WP_W);
        #pragma unroll 4
        for (int idx = tid; idx < 9216; idx += 256) {
            int qq = idx & 3;
            int n  = (idx >> 2) & 63;
            int t  = idx >> 8;
            int k0 = 16 * t + 2 * qq;
            uint2 o;
            o.x = pack_h2(w[k0 * 64 + n],       w[(k0 + 1) * 64 + n]);
            o.y = pack_h2(w[(k0 + 8) * 64 + n], w[(k0 + 9) * 64 + n]);
            wsm[idx] = o;
        }
        if (tid < 64) {
            float s = gm[tid] * rsqrtf(vr[tid] + 1e-3f);
            sm[S_SCALE_W + tid] = s;
            sm[S_BIAS_W + tid]  = cb[tid] * s + bt[tid] - mn[tid] * s;
        }
    }

    const int rb = wid * 2;              // warp's pixel-row base (2 of 16 rows)
    const uint2* bp2 = (const uint2*)(sm + S_WP_W);

    // ---- prologue: start loading first item's half0 ----
    int gr0, gc0;
    {
        const int it0 = blockIdx.x;      // always < NCONV (148 < 1024)
        const int b = it0 >> 1, sub = it0 & 1;
        gr0 = abi[3 * b + 1] * 32 + sub * 16;
        gc0 = abi[3 * b + 2] * 32;
        issue_half(inp, gr0, gc0, 0, stg_u32, tid);
        cp_commit();
    }

    for (int it = blockIdx.x; it < NTOT; it += gridDim.x) {
        if (it < NCONV) {
            // ---- h0 staged -> convert; then start h1 into stage ----
            cp_wait0();
            __syncthreads();
            convert_half(sm + S_STG_W, (uint32_t*)(sm + S_F0_W), tid);
            __syncthreads();             // all convert reads of stage done
            issue_half(inp, gr0, gc0, 1, stg_u32, tid);
            cp_commit();

            float acc[4][8][4];
            #pragma unroll
            for (int a = 0; a < 4; a++)
                #pragma unroll
                for (int c = 0; c < 8; c++)
                    #pragma unroll
                    for (int d = 0; d < 4; d++) acc[a][c][d] = 0.f;

            COMPUTE_HALF16(S_F0_W, 0)    // overlaps h1 load

            // ---- h1 staged -> convert; then start next item's h0 ----
            cp_wait0();
            __syncthreads();
            convert_half(sm + S_STG_W, (uint32_t*)(sm + S_F1_W), tid);
            __syncthreads();

            const int itn = it + gridDim.x;
            int grn = 0, gcn = 0;
            if (itn < NCONV) {
                const int b = itn >> 1, sub = itn & 1;
                grn = abi[3 * b + 1] * 32 + sub * 16;
                gcn = abi[3 * b + 2] * 32;
                issue_half(inp, grn, gcn, 0, stg_u32, tid);
            }
            cp_commit();

            COMPUTE_HALF16(S_F1_W, 1)    // overlaps next h0 load

            // ---- epilogue: fused BN scale/bias + ReLU ----
            #pragma unroll
            for (int mf = 0; mf < 4; mf++) {
                const int gpr = gr0 + rb + (mf & 1);
                const int gpc = gc0 + ((mf >> 1) << 4) + grp;
                #pragma unroll
                for (int nf = 0; nf < 8; nf++) {
                    const int n0 = nf * 8 + 2 * q;
                    const float s0 = sm[S_SCALE_W + n0], s1 = sm[S_SCALE_W + n0 + 1];
                    const float d0 = sm[S_BIAS_W + n0],  d1 = sm[S_BIAS_W + n0 + 1];
                    float* p0 = out + ((size_t)gpr * HW + gpc) * 64 + n0;
                    float2 v0, v1;
                    v0.x = fmaxf(fmaf(acc[mf][nf][0], s0, d0), 0.f);
                    v0.y = fmaxf(fmaf(acc[mf][nf][1], s1, d1), 0.f);
                    v1.x = fmaxf(fmaf(acc[mf][nf][2], s0, d0), 0.f);
                    v1.y = fmaxf(fmaf(acc[mf][nf][3], s1, d1), 0.f);
                    __stcs((float2*)p0, v0);
                    __stcs((float2*)(p0 + 8 * 64), v1);    // px col gpc+8
                }
            }
            gr0 = grn; gc0 = gcn;
        } else {
            // ================= zero-fill item =================
            const int blk = it - NCONV;
            int lo = 0, hi = 511, found = 0;
            while (lo <= hi) {
                int mid = (lo + hi) >> 1;
                int f = abi[3 * mid + 1] * 32 + abi[3 * mid + 2];
                if (f == blk) { found = 1; break; }
                if (f < blk) lo = mid + 1; else hi = mid - 1;
            }
            if (!found) {
                const int bi = blk >> 5, bj = blk & 31;
                const float4 z = make_float4(0.f, 0.f, 0.f, 0.f);
                #pragma unroll 8
                for (int j = 0; j < 64; j++) {
                    int idx = tid + j * 256;          // 0..16383 float4s
                    int r   = idx >> 9;               // 512 float4 per pixel row
                    int c4  = idx & 511;
                    __stcs((float4*)(out + ((size_t)(bi * 32 + r) * HW + bj * 32) * 64) + c4, z);
                }
            }
        }
    }
    cp_wait0();                          // drain any in-flight cp.async
}

// ====================== launch =================================
extern "C" void kernel_launch(void* const* d_in, const int* in_sizes, int n_in,
                              void* d_out, int out_size) {
    const float* inp   = (const float*)d_in[0];
    const float* w     = (const float*)d_in[1];
    const float* cb    = (const float*)d_in[2];
    const float* gamma = (const float*)d_in[3];
    const float* beta  = (const float*)d_in[4];
    const float* mean  = (const float*)d_in[5];
    const float* var   = (const float*)d_in[6];
    const int*   abi   = (const int*)d_in[7];
    float* out = (float*)d_out;

    cudaFuncSetAttribute(convk, cudaFuncAttributeMaxDynamicSharedMemorySize, S_TOTAL_B);
    convk<<<148, 256, S_TOTAL_B>>>(inp, w, cb, gamma, beta, mean, var, abi, out);
}